// round 16
// baseline (speedup 1.0000x reference)
#include <cuda_runtime.h>
#include <cstdint>

#define N 8192
#define IN_F 512
#define OUT_F 64
#define SS 512

#define STAGES 6
#define ROW_BYTES (N * 4)
#define SM_MAIN_TOTAL (STAGES * ROW_BYTES + 16 * 16 * 4)

// ---------------- device scratch (static) ----------------
__device__ float g_R[N];                           // exp(-0.8 * s1_i)
__device__ __align__(16) float2 g_EP[N];           // (exp(s2_j), exp(0.2*s2_j))
__device__ __align__(16) float g_part[512 * N];    // 16MB per-block partial colsums
__device__ float g_colsumf[N];

__device__ __forceinline__ uint32_t smem_u32(const void* p) {
    uint32_t a;
    asm("{ .reg .u64 tmp; cvta.to.shared.u64 tmp, %1; cvt.u32.u64 %0, tmp; }"
        : "=r"(a) : "l"(p));
    return a;
}
// 16B async copy; variant D carries a dummy float dependency to order the
// smem write after this thread's consumption of the stage being overwritten.
#define CP16(dst, src) \
    asm volatile("cp.async.cg.shared.global [%0], [%1], 16;" :: "r"(dst), "l"(src) : "memory")
#define CP16D(dst, src, dep) \
    asm volatile("cp.async.cg.shared.global [%0], [%1], 16;" :: "r"(dst), "l"(src), "f"(dep) : "memory")
#define CP_COMMIT() asm volatile("cp.async.commit_group;" ::: "memory")
#define CP_WAIT(n)  asm volatile("cp.async.wait_group %0;" :: "n"(n) : "memory")

__global__ void k_nop() {}

// ---------------- s1,s2 = input @ (W@a)  ->  R_i, (ex_j, ey_j) ----------------
__global__ void k_s(const float* __restrict__ in, const float* __restrict__ W,
                    const float* __restrict__ a) {
    __shared__ float swa[2 * IN_F];
    int t = threadIdx.x;
#pragma unroll
    for (int half = 0; half < 2; half++) {
        int m = t + half * 256;
        const float4* w4 = (const float4*)(W + m * OUT_F);
        float s1 = 0.f, s2 = 0.f;
#pragma unroll
        for (int q = 0; q < OUT_F / 4; q++) {
            float4 wv = __ldg(w4 + q);
            s1 += wv.x * __ldg(a + 4 * q + 0) + wv.y * __ldg(a + 4 * q + 1)
                + wv.z * __ldg(a + 4 * q + 2) + wv.w * __ldg(a + 4 * q + 3);
            s2 += wv.x * __ldg(a + OUT_F + 4 * q + 0) + wv.y * __ldg(a + OUT_F + 4 * q + 1)
                + wv.z * __ldg(a + OUT_F + 4 * q + 2) + wv.w * __ldg(a + OUT_F + 4 * q + 3);
        }
        swa[m] = s1;
        swa[IN_F + m] = s2;
    }
    __syncthreads();

    int warp = t >> 5, lane = t & 31;
    int row = blockIdx.x * 8 + warp;
    const float* ir = in + (size_t)row * IN_F;
    float s1 = 0.f, s2 = 0.f;
#pragma unroll
    for (int q = 0; q < IN_F / 32; q++) {
        float x = __ldg(ir + q * 32 + lane);
        s1 = fmaf(x, swa[q * 32 + lane], s1);
        s2 = fmaf(x, swa[IN_F + q * 32 + lane], s2);
    }
#pragma unroll
    for (int o = 16; o; o >>= 1) {
        s1 += __shfl_xor_sync(0xFFFFFFFFu, s1, o);
        s2 += __shfl_xor_sync(0xFFFFFFFFu, s2, o);
    }
    if (lane == 0) {
        double d1 = (double)s1, d2 = (double)s2;
        g_R[row] = (float)exp(-0.8 * d1);
        g_EP[row] = make_float2((float)exp(d2), (float)exp(0.2 * d2));
    }
}

// ---------------- cp.async-pipelined two-phase masked-softmax ----------------
// 512 blocks x 512 threads; block owns 16 rows; thread owns 16 fixed columns
// (column(g,e) = g*2048+4t+e). Each thread streams ITS OWN 4x16B chunks per row
// through a 6-stage smem ring (self-produced/self-consumed -> no block barrier).
// Arithmetic order identical to R12's k_main -> bit-exact result.
__global__ void __launch_bounds__(512, 1) k_main(const int* __restrict__ adj) {
    extern __shared__ char smem[];
    float* sZ = (float*)(smem + STAGES * ROW_BYTES);   // [16 rows][16 warps]
    uint32_t sb = smem_u32(smem);
    int t = threadIdx.x;
    int warp = t >> 5, lane = t & 31;
    int row0 = blockIdx.x * 16;

    float ex[16], ey[16];
    const float4* ep4 = (const float4*)g_EP;
#pragma unroll
    for (int g = 0; g < 4; g++) {
#pragma unroll
        for (int q = 0; q < 2; q++) {
            float4 v = __ldg(ep4 + g * 1024 + 2 * t + q);
            ex[g * 4 + 2 * q + 0] = v.x; ey[g * 4 + 2 * q + 0] = v.y;
            ex[g * 4 + 2 * q + 1] = v.z; ey[g * 4 + 2 * q + 1] = v.w;
        }
    }

    // prologue: rows 0..5 into stages 0..5 (one commit group per row)
#pragma unroll
    for (int d = 0; d < STAGES; d++) {
        const char* src = (const char*)(adj + (size_t)(row0 + d) * N);
#pragma unroll
        for (int g = 0; g < 4; g++)
            CP16(sb + d * ROW_BYTES + (g * 512 + t) * 16, src + (g * 512 + t) * 16);
        CP_COMMIT();
    }

    uint32_t m[16];

    // ---- Phase A: barrier-free streaming through the ring ----
#pragma unroll
    for (int r = 0; r < 16; r++) {
        // wait until row r's group is complete (compile-time descending tail)
        if (r < 10) CP_WAIT(STAGES - 1);
        else if (r == 10) CP_WAIT(5);
        else if (r == 11) CP_WAIT(4);
        else if (r == 12) CP_WAIT(3);
        else if (r == 13) CP_WAIT(2);
        else if (r == 14) CP_WAIT(1);
        else CP_WAIT(0);

        const int4* st = (const int4*)(smem + (r % STAGES) * ROW_BYTES);
        float R = __ldg(g_R + row0 + r);
        float w[16];
        float z = 0.f;
        uint32_t mask = 0;
#pragma unroll
        for (int g = 0; g < 4; g++) {
            int4 A = st[g * 512 + t];              // conflict-free LDS.128 (own data)
            float w0 = fmaxf(ex[g * 4 + 0], R * ey[g * 4 + 0]);
            float w1 = fmaxf(ex[g * 4 + 1], R * ey[g * 4 + 1]);
            float w2 = fmaxf(ex[g * 4 + 2], R * ey[g * 4 + 2]);
            float w3 = fmaxf(ex[g * 4 + 3], R * ey[g * 4 + 3]);
            uint32_t b0 = (A.x > 0) ? 1u : 0u;
            uint32_t b1 = (A.y > 0) ? 1u : 0u;
            uint32_t b2 = (A.z > 0) ? 1u : 0u;
            uint32_t b3 = (A.w > 0) ? 1u : 0u;
            mask |= (b0 << (g * 4)) | (b1 << (g * 4 + 1))
                  | (b2 << (g * 4 + 2)) | (b3 << (g * 4 + 3));
            w0 = b0 ? w0 : 0.f;
            w1 = b1 ? w1 : 0.f;
            w2 = b2 ? w2 : 0.f;
            w3 = b3 ? w3 : 0.f;
            w[g * 4 + 0] = w0; w[g * 4 + 1] = w1;
            w[g * 4 + 2] = w2; w[g * 4 + 3] = w3;
            z += (w0 + w1) + (w2 + w3);            // same pairwise order as R12
        }
        m[r] = mask;
        // refill stage (r%6) with row r+6; z-dependency orders it after consumption
        if (r + STAGES < 16) {
            const char* src = (const char*)(adj + (size_t)(row0 + r + STAGES) * N);
#pragma unroll
            for (int g = 0; g < 4; g++)
                CP16D(sb + (r % STAGES) * ROW_BYTES + (g * 512 + t) * 16,
                      src + (g * 512 + t) * 16, z);
            CP_COMMIT();
        }
#pragma unroll
        for (int o = 16; o; o >>= 1) z += __shfl_xor_sync(0xFFFFFFFFu, z, o);
        if (lane == 0) sZ[r * 16 + warp] = z;
    }
    __syncthreads();                               // the ONLY block barrier

    // ---- Phase B: no memory, recompute + accumulate (identical to R12) ----
    float acc[16];
#pragma unroll
    for (int k = 0; k < 16; k++) acc[k] = 0.f;
#pragma unroll
    for (int r = 0; r < 16; r++) {
        float zt = 0.f;
#pragma unroll
        for (int q = 0; q < 16; q++) zt += sZ[r * 16 + q];
        float invZ = (zt > 0.f) ? (1.0f / zt) : 0.f;
        float R = __ldg(g_R + row0 + r);
        uint32_t mask = m[r];
#pragma unroll
        for (int k = 0; k < 16; k++) {
            float w0 = fmaxf(ex[k], R * ey[k]);
            float val = (mask >> k) & 1u ? w0 : 0.f;
            acc[k] = fmaf(val, invZ, acc[k]);
        }
    }

    float4* part4 = (float4*)(g_part + (size_t)blockIdx.x * N);
#pragma unroll
    for (int g = 0; g < 4; g++)
        part4[g * 512 + t] = make_float4(acc[g * 4 + 0], acc[g * 4 + 1],
                                         acc[g * 4 + 2], acc[g * 4 + 3]);
}

// ---------------- deterministic column reduction (R12/R13 measured version) ----
__global__ void __launch_bounds__(256) k_reduce() {
    __shared__ float sd[8][32];
    int t = threadIdx.x;
    int v = t & 31;
    int u = t >> 5;
    int c = blockIdx.x * 32 + v;
    float s = 0.f;
    int b0 = u * 64;
#pragma unroll 8
    for (int b = b0; b < b0 + 64; b++)
        s += g_part[(size_t)b * N + c];
    sd[u][v] = s;
    __syncthreads();
    if (u == 0) {
        double tot = 0.0;
#pragma unroll
        for (int q = 0; q < 8; q++) tot += (double)sd[q][v];
        g_colsumf[c] = (float)tot;
    }
}

// ---------------- exact top-512 via brute-force ranking ----------------
__global__ void __launch_bounds__(256) k_rank(float* __restrict__ out) {
    __shared__ uint32_t sc[N];
    __shared__ int sr[256];
    int t = threadIdx.x;
    const float4* cs4 = (const float4*)g_colsumf;
    uint4* sc4 = (uint4*)sc;
#pragma unroll
    for (int p = 0; p < N / 4 / 256; p++) {
        float4 v = __ldg(cs4 + p * 256 + t);
        sc4[p * 256 + t] = make_uint4(__float_as_uint(v.x), __float_as_uint(v.y),
                                      __float_as_uint(v.z), __float_as_uint(v.w));
    }
    __syncthreads();

    int jl  = t & 15;
    int seg = t >> 4;
    int j = blockIdx.x * 16 + jl;
    uint32_t sj = sc[j];
    int rank = 0;
    int p0 = seg * (N / 16);
#pragma unroll 4
    for (int p = p0; p < p0 + N / 16; p++) {
        uint32_t sp = sc[p];
        rank += (sp > sj) || (sp == sj && p < j);
    }
    sr[t] = rank;
    __syncthreads();
    if (t < 16) {
        int total = 0;
#pragma unroll
        for (int s = 0; s < 16; s++) total += sr[t + 16 * s];
        if (total < SS) out[total] = (float)j;
    }
}

// ---------------- launch (k_main in the profiled 4th slot) ----------------
extern "C" void kernel_launch(void* const* d_in, const int* in_sizes, int n_in,
                              void* d_out, int out_size) {
    const float* input = nullptr;
    const int*   adj   = nullptr;
    const float* W     = nullptr;
    const float* a     = nullptr;
    for (int i = 0; i < n_in; i++) {
        long long s = in_sizes[i];
        if      (s == (long long)N * IN_F)     input = (const float*)d_in[i];
        else if (s == (long long)N * N)        adj   = (const int*)d_in[i];
        else if (s == (long long)IN_F * OUT_F) W     = (const float*)d_in[i];
        else if (s == 2 * OUT_F)               a     = (const float*)d_in[i];
    }
    if (!input || !adj || !W || !a) {
        input = (const float*)d_in[0];
        adj   = (const int*)d_in[1];
        W     = (const float*)d_in[2];
        a     = (const float*)d_in[3];
    }
    float* out = (float*)d_out;

    cudaFuncSetAttribute(k_main, cudaFuncAttributeMaxDynamicSharedMemorySize,
                         SM_MAIN_TOTAL);

    k_s<<<N / 8, 256>>>(input, W, a);
    k_nop<<<1, 32>>>();
    k_nop<<<1, 32>>>();
    k_main<<<512, 512, SM_MAIN_TOTAL>>>(adj);
    k_reduce<<<N / 32, 256>>>();
    k_rank<<<N / 16, 256>>>(out);
}